// round 2
// baseline (speedup 1.0000x reference)
#include <cuda_runtime.h>

// ---------------------------------------------------------------------------
// EncoderBiLSTMMaxPool: 2-layer bidirectional LSTM, hidden state carried
// across samples with reset every 32 samples -> 4 independent chains.
//
// Phases (all on default stream, graph-capturable):
//   1. embed:  emb[b,s,:] = E_rt[rt] + E_re[re] + E_rm[rm]            (16384 x 512)
//   2. gemm:   gx = input @ Wih[l]^T + (bih+bhh)                      (16384 x 2048)
//   3. lstm:   recurrence for layer l, both dirs, 4 groups in parallel
//   4. (repeat 2,3 for layer 1, writing layer-1 outputs into d_out)
//   5. maxpool over batch axis -> (S, H)
// ---------------------------------------------------------------------------

#define Bn   128
#define Sn   128
#define Hn   512
#define HHn  256
#define NROW 16384      // B*S
#define GXN  2048       // 2 dirs * 4 gates * 256

// scratch (device globals: allocation-free rule)
__device__ float g_emb[NROW * Hn];     // 33.5 MB
__device__ float g_x  [NROW * GXN];    // 134 MB
__device__ float g_y0 [NROW * Hn];     // 33.5 MB  (layer-0 output)

// ---------------------------------------------------------------------------
// helpers
// ---------------------------------------------------------------------------
__device__ __forceinline__ unsigned smem_u32(const void* p) {
    return (unsigned)__cvta_generic_to_shared(p);
}
__device__ __forceinline__ unsigned mapa_cluster(unsigned addr, unsigned rank) {
    unsigned r;
    asm volatile("mapa.shared::cluster.u32 %0, %1, %2;" : "=r"(r) : "r"(addr), "r"(rank));
    return r;
}
__device__ __forceinline__ void st_cluster_f32(unsigned addr, float v) {
    asm volatile("st.shared::cluster.f32 [%0], %1;" :: "r"(addr), "f"(v) : "memory");
}
__device__ __forceinline__ void cluster_sync_() {
    asm volatile("barrier.cluster.arrive.aligned;" ::: "memory");
    asm volatile("barrier.cluster.wait.aligned;" ::: "memory");
}
__device__ __forceinline__ float sigmoidf_(float x) {
    return 1.0f / (1.0f + __expf(-x));
}

// ---------------------------------------------------------------------------
// 1) embedding sum: one block per (b,s) row, 128 threads x float4
// ---------------------------------------------------------------------------
__global__ void embed_kernel(const int* __restrict__ rt, const int* __restrict__ re,
                             const int* __restrict__ rm,
                             const float* __restrict__ Ert, const float* __restrict__ Ere,
                             const float* __restrict__ Erm)
{
    int row = blockIdx.x;            // 0..16383
    int t   = threadIdx.x;           // 0..127
    long irt = rt[row], ire = re[row], irm = rm[row];
    const float4* a = (const float4*)(Ert + irt * (long)Hn);
    const float4* b = (const float4*)(Ere + ire * (long)Hn);
    const float4* c = (const float4*)(Erm + irm * (long)Hn);
    float4 va = a[t], vb = b[t], vc = c[t];
    float4 o;
    o.x = va.x + vb.x + vc.x;
    o.y = va.y + vb.y + vc.y;
    o.z = va.z + vb.z + vc.z;
    o.w = va.w + vb.w + vc.w;
    ((float4*)(g_emb + (long)row * Hn))[t] = o;
}

// ---------------------------------------------------------------------------
// 2) fp32 GEMM:  C[m,n] = sum_k A[m,k] * W[n,k] + bih[n] + bhh[n]
//    M=16384, N=2048, K=512.  Tiles: BM=128, BN=64, BK=16, 256 thr, 8x4 micro.
// ---------------------------------------------------------------------------
__global__ __launch_bounds__(256) void gemm_kernel(
    const float* __restrict__ A, const float* __restrict__ W,
    const float* __restrict__ bih, const float* __restrict__ bhh,
    float* __restrict__ C)
{
    __shared__ float As[16][128];
    __shared__ float Ws[16][64];

    const int bm = blockIdx.y * 128;
    const int bn = blockIdx.x * 64;
    const int tid = threadIdx.x;
    const int tx = tid & 15;     // n
    const int ty = tid >> 4;     // m

    float acc[8][4];
#pragma unroll
    for (int i = 0; i < 8; i++)
#pragma unroll
        for (int j = 0; j < 4; j++) acc[i][j] = 0.f;

    for (int k0 = 0; k0 < 512; k0 += 16) {
        // load A tile: 128x16 = 512 float4, 2 per thread
#pragma unroll
        for (int i = 0; i < 2; i++) {
            int f4 = tid * 2 + i;
            int r = f4 >> 2, c4 = f4 & 3;
            float4 v = *(const float4*)(A + (long)(bm + r) * 512 + k0 + c4 * 4);
            As[c4 * 4 + 0][r] = v.x;
            As[c4 * 4 + 1][r] = v.y;
            As[c4 * 4 + 2][r] = v.z;
            As[c4 * 4 + 3][r] = v.w;
        }
        // load W tile: 64x16 = 256 float4, 1 per thread
        {
            int r = tid >> 2, c4 = tid & 3;
            float4 v = *(const float4*)(W + (long)(bn + r) * 512 + k0 + c4 * 4);
            Ws[c4 * 4 + 0][r] = v.x;
            Ws[c4 * 4 + 1][r] = v.y;
            Ws[c4 * 4 + 2][r] = v.z;
            Ws[c4 * 4 + 3][r] = v.w;
        }
        __syncthreads();
#pragma unroll
        for (int k = 0; k < 16; k++) {
            float a[8], w[4];
            *(float4*)(a)     = *(const float4*)&As[k][ty * 8];
            *(float4*)(a + 4) = *(const float4*)&As[k][ty * 8 + 4];
            *(float4*)(w)     = *(const float4*)&Ws[k][tx * 4];
#pragma unroll
            for (int i = 0; i < 8; i++)
#pragma unroll
                for (int j = 0; j < 4; j++) acc[i][j] += a[i] * w[j];
        }
        __syncthreads();
    }

#pragma unroll
    for (int j = 0; j < 4; j++) {
        int n = bn + tx * 4 + j;
        float bias = bih[n] + bhh[n];
#pragma unroll
        for (int i = 0; i < 8; i++) {
            int m = bm + ty * 8 + i;
            C[(long)m * GXN + n] = acc[i][j] + bias;
        }
    }
}

// ---------------------------------------------------------------------------
// 3) LSTM recurrence for one layer. Grid = 64 CTAs = 8 clusters of 8.
//    cluster c: group = c&3, dir = c>>2. Each CTA owns 32 unit indices
//    (128 gate rows). Whh rows live in registers (128 fp32 / thread).
//    h exchanged via DSMEM + barrier.cluster each step (double buffered).
// ---------------------------------------------------------------------------
__global__ void __cluster_dims__(8, 1, 1) __launch_bounds__(256, 1)
lstm_layer_kernel(const float* __restrict__ Whh, const float* __restrict__ gx,
                  float* __restrict__ y, const float* __restrict__ h0,
                  const float* __restrict__ c0, int layer)
{
    __shared__ __align__(16) float h_buf[2][256];
    __shared__ float partial[256];
    __shared__ float gates_sm[128];
    __shared__ float c_state[32];

    unsigned rank;
    asm("mov.u32 %0, %%cluster_ctarank;" : "=r"(rank));
    const int cluster_id = blockIdx.x >> 3;
    const int group = cluster_id & 3;
    const int dir   = cluster_id >> 2;
    const int tid = threadIdx.x;          // 0..255
    const int row_local = tid & 127;      // gate row within CTA
    const int half = tid >> 7;            // which K-half (0: k<128, 1: k>=128)
    const int gate = row_local >> 5;      // 0..3 (i,f,g,o)
    const int ul   = row_local & 31;      // unit within CTA
    const int unit = (int)rank * 32 + ul; // 0..255 global unit
    const int grow = gate * 256 + unit;   // 0..1023 global gate row

    // --- weights into registers ---
    float4 w4[32];
    const float4* wsrc = (const float4*)(Whh
        + ((long)(layer * 2 + dir) * 1024 + grow) * 256 + half * 128);
#pragma unroll
    for (int j = 0; j < 32; j++) w4[j] = wsrc[j];

    // --- state init ---
    const int sidx = (layer * 2 + dir) * 256;
    h_buf[0][tid & 255] = (group == 0) ? h0[sidx + tid] : 0.f;   // tid covers 0..255
    if (tid < 32) c_state[tid] = (group == 0) ? c0[sidx + unit] : 0.f;

    cluster_sync_();

    const int xcol = dir * 1024 + grow;   // column in gx for this gate row
    const int ycol = dir * 256 + unit;    // column in y for this unit

    int step = 0;
    for (int si = 0; si < 32; si++) {
        const int b = group * 32 + si;
        for (int ti = 0; ti < 128; ti++) {
            const int t = dir ? (127 - ti) : ti;
            const long m = (long)b * 128 + t;

            float xval = 0.f;
            if (tid < 128) xval = __ldg(gx + m * GXN + xcol);    // prefetch early

            const int par = step & 1;
            const float4* hb = (const float4*)(h_buf[par]) + half * 32;
            float acc0 = 0.f, acc1 = 0.f;
#pragma unroll
            for (int j = 0; j < 32; j += 2) {
                float4 hv = hb[j];     float4 wv = w4[j];
                acc0 += hv.x * wv.x; acc0 += hv.y * wv.y;
                acc0 += hv.z * wv.z; acc0 += hv.w * wv.w;
                float4 hv2 = hb[j + 1]; float4 wv2 = w4[j + 1];
                acc1 += hv2.x * wv2.x; acc1 += hv2.y * wv2.y;
                acc1 += hv2.z * wv2.z; acc1 += hv2.w * wv2.w;
            }
            partial[tid] = acc0 + acc1;
            __syncthreads();
            if (tid < 128)
                gates_sm[tid] = partial[tid] + partial[tid + 128] + xval;
            __syncthreads();
            if (tid < 32) {
                float ig = sigmoidf_(gates_sm[tid]);
                float fg = sigmoidf_(gates_sm[32 + tid]);
                float gg = tanhf(gates_sm[64 + tid]);
                float og = sigmoidf_(gates_sm[96 + tid]);
                float c = fg * c_state[tid] + ig * gg;
                c_state[tid] = c;
                float h = og * tanhf(c);
                y[m * Hn + ycol] = h;
                // broadcast new h to every CTA's other buffer
                unsigned laddr = smem_u32(&h_buf[par ^ 1][(int)rank * 32 + tid]);
#pragma unroll
                for (unsigned r = 0; r < 8; r++)
                    st_cluster_f32(mapa_cluster(laddr, r), h);
            }
            cluster_sync_();
            step++;
        }
    }
}

// ---------------------------------------------------------------------------
// 5) max over batch axis: out2[s,h] = max_b y1[b,s,h]
// ---------------------------------------------------------------------------
__global__ void maxpool_kernel(const float* __restrict__ y1, float* __restrict__ out2)
{
    int idx = blockIdx.x * 256 + threadIdx.x;    // 0..65535
    int s = idx >> 9, h = idx & 511;
    float mx = -3.402823466e38f;
    for (int b = 0; b < 128; b++) {
        float v = y1[((long)b * 128 + s) * Hn + h];
        mx = fmaxf(mx, v);
    }
    out2[idx] = mx;
}

// ---------------------------------------------------------------------------
extern "C" void kernel_launch(void* const* d_in, const int* in_sizes, int n_in,
                              void* d_out, int out_size)
{
    const int*   rt  = (const int*)d_in[0];
    const int*   re  = (const int*)d_in[1];
    const int*   rm  = (const int*)d_in[2];
    const float* h0  = (const float*)d_in[3];
    const float* c0  = (const float*)d_in[4];
    const float* Ert = (const float*)d_in[5];
    const float* Ere = (const float*)d_in[6];
    const float* Erm = (const float*)d_in[7];
    const float* Wih = (const float*)d_in[8];   // (2,2,1024,512)
    const float* Whh = (const float*)d_in[9];   // (2,2,1024,256)
    const float* bih = (const float*)d_in[10];  // (2,2,1024)
    const float* bhh = (const float*)d_in[11];

    float* out  = (float*)d_out;
    float* y1   = out;                       // bilstm_outs (128,128,512)
    float* out2 = out + (long)Bn * Sn * Hn;  // output (128,512)

    void *p_emb = nullptr, *p_x = nullptr, *p_y0 = nullptr;
    cudaGetSymbolAddress(&p_emb, g_emb);
    cudaGetSymbolAddress(&p_x,   g_x);
    cudaGetSymbolAddress(&p_y0,  g_y0);
    float* emb = (float*)p_emb;
    float* gx  = (float*)p_x;
    float* y0  = (float*)p_y0;

    // 1) embeddings
    embed_kernel<<<NROW, 128>>>(rt, re, rm, Ert, Ere, Erm);

    dim3 ggrid(GXN / 64, NROW / 128);   // (32, 128)

    // 2) layer 0 input GEMM
    gemm_kernel<<<ggrid, 256>>>(emb, Wih, bih, bhh, gx);
    // 3) layer 0 recurrence
    lstm_layer_kernel<<<64, 256>>>(Whh, gx, y0, h0, c0, 0);
    // 4) layer 1 input GEMM (input = layer-0 output)
    gemm_kernel<<<ggrid, 256>>>(y0, Wih + (long)1 * 2 * 1024 * 512,
                                bih + 2048, bhh + 2048, gx);
    // layer 1 recurrence, writing straight into d_out
    lstm_layer_kernel<<<64, 256>>>(Whh, gx, y1, h0, c0, 1);
    // 5) max over batch
    maxpool_kernel<<<(Bn * Hn * Sn / Sn) / 256 * 2, 256>>>(y1, out2);
}

// round 3
// speedup vs baseline: 2.1730x; 2.1730x over previous
#include <cuda_runtime.h>

// ---------------------------------------------------------------------------
// EncoderBiLSTMMaxPool: 2-layer bidirectional LSTM, hidden state carried
// across samples with reset every 32 samples -> 4 independent chains.
//
//   1. embed:  emb = E_rt[rt] + E_re[re] + E_rm[rm]          (16384 x 512)
//   2. gemm:   gx  = input @ Wih[l]^T + (bih+bhh)            (16384 x 2048)
//   3. lstm:   recurrence, 8 clusters (4 groups x 2 dirs) of 8 CTAs
//              h exchanged via st.async + tx-counting mbarriers (no cluster.sync)
//   4. repeat 2,3 for layer 1 (into d_out)
//   5. maxpool over batch axis -> (S, H)
// ---------------------------------------------------------------------------

#define Bn   128
#define Sn   128
#define Hn   512
#define HHn  256
#define NROW 16384
#define GXN  2048

typedef unsigned long long ull;

__device__ float g_emb[NROW * Hn];
__device__ float g_x  [NROW * GXN];
__device__ float g_y0 [NROW * Hn];

// ---------------------------------------------------------------------------
// helpers
// ---------------------------------------------------------------------------
__device__ __forceinline__ unsigned smem_u32(const void* p) {
    return (unsigned)__cvta_generic_to_shared(p);
}
__device__ __forceinline__ unsigned mapa_cluster(unsigned addr, unsigned rank) {
    unsigned r;
    asm volatile("mapa.shared::cluster.u32 %0, %1, %2;" : "=r"(r) : "r"(addr), "r"(rank));
    return r;
}
__device__ __forceinline__ void cluster_sync_() {
    asm volatile("barrier.cluster.arrive.aligned;" ::: "memory");
    asm volatile("barrier.cluster.wait.aligned;" ::: "memory");
}
__device__ __forceinline__ void mbar_init(unsigned bar, unsigned cnt) {
    asm volatile("mbarrier.init.shared.b64 [%0], %1;" :: "r"(bar), "r"(cnt) : "memory");
}
// arrive (count 1) + add expected transaction bytes for this phase
__device__ __forceinline__ void mbar_arm(unsigned bar, unsigned tx) {
    asm volatile("mbarrier.arrive.expect_tx.shared::cta.b64 _, [%0], %1;"
                 :: "r"(bar), "r"(tx) : "memory");
}
__device__ __forceinline__ void mbar_wait(unsigned bar, unsigned parity) {
    asm volatile(
        "{\n\t.reg .pred P;\n"
        "LW%=:\n\t"
        "mbarrier.try_wait.parity.acquire.cta.shared::cta.b64 P, [%0], %1, 0x989680;\n\t"
        "@!P bra LW%=;\n\t}"
        :: "r"(bar), "r"(parity) : "memory");
}
// remote SMEM store that bumps the tx-count of the mbarrier co-located with dst
__device__ __forceinline__ void st_async_f32(unsigned dst, float v, unsigned bar) {
    asm volatile("st.async.shared::cluster.mbarrier::complete_tx::bytes.b32 [%0], %1, [%2];"
                 :: "r"(dst), "r"(__float_as_uint(v)), "r"(bar) : "memory");
}
__device__ __forceinline__ float tanh_fast(float x) {
    float r;
    asm("tanh.approx.f32 %0, %1;" : "=f"(r) : "f"(x));
    return r;
}
__device__ __forceinline__ float sigmoid_fast(float x) {
    return fmaf(0.5f, tanh_fast(0.5f * x), 0.5f);
}
__device__ __forceinline__ void fma2(ull& acc, ull a, ull b) {
    asm("fma.rn.f32x2 %0, %1, %2, %0;" : "+l"(acc) : "l"(a), "l"(b));
}
__device__ __forceinline__ float sum2(ull a) {
    unsigned lo, hi;
    asm("mov.b64 {%0,%1}, %2;" : "=r"(lo), "=r"(hi) : "l"(a));
    return __uint_as_float(lo) + __uint_as_float(hi);
}

// ---------------------------------------------------------------------------
// 1) embedding sum
// ---------------------------------------------------------------------------
__global__ void embed_kernel(const int* __restrict__ rt, const int* __restrict__ re,
                             const int* __restrict__ rm,
                             const float* __restrict__ Ert, const float* __restrict__ Ere,
                             const float* __restrict__ Erm)
{
    int row = blockIdx.x;
    int t   = threadIdx.x;
    long irt = rt[row], ire = re[row], irm = rm[row];
    const float4* a = (const float4*)(Ert + irt * (long)Hn);
    const float4* b = (const float4*)(Ere + ire * (long)Hn);
    const float4* c = (const float4*)(Erm + irm * (long)Hn);
    float4 va = a[t], vb = b[t], vc = c[t];
    float4 o;
    o.x = va.x + vb.x + vc.x;
    o.y = va.y + vb.y + vc.y;
    o.z = va.z + vb.z + vc.z;
    o.w = va.w + vb.w + vc.w;
    ((float4*)(g_emb + (long)row * Hn))[t] = o;
}

// ---------------------------------------------------------------------------
// 2) fp32 GEMM (unchanged from R2 — known correct; tensor-core rewrite is next)
// ---------------------------------------------------------------------------
__global__ __launch_bounds__(256) void gemm_kernel(
    const float* __restrict__ A, const float* __restrict__ W,
    const float* __restrict__ bih, const float* __restrict__ bhh,
    float* __restrict__ C)
{
    __shared__ float As[16][128];
    __shared__ float Ws[16][64];

    const int bm = blockIdx.y * 128;
    const int bn = blockIdx.x * 64;
    const int tid = threadIdx.x;
    const int tx = tid & 15;
    const int ty = tid >> 4;

    float acc[8][4];
#pragma unroll
    for (int i = 0; i < 8; i++)
#pragma unroll
        for (int j = 0; j < 4; j++) acc[i][j] = 0.f;

    for (int k0 = 0; k0 < 512; k0 += 16) {
#pragma unroll
        for (int i = 0; i < 2; i++) {
            int f4 = tid * 2 + i;
            int r = f4 >> 2, c4 = f4 & 3;
            float4 v = *(const float4*)(A + (long)(bm + r) * 512 + k0 + c4 * 4);
            As[c4 * 4 + 0][r] = v.x;
            As[c4 * 4 + 1][r] = v.y;
            As[c4 * 4 + 2][r] = v.z;
            As[c4 * 4 + 3][r] = v.w;
        }
        {
            int r = tid >> 2, c4 = tid & 3;
            float4 v = *(const float4*)(W + (long)(bn + r) * 512 + k0 + c4 * 4);
            Ws[c4 * 4 + 0][r] = v.x;
            Ws[c4 * 4 + 1][r] = v.y;
            Ws[c4 * 4 + 2][r] = v.z;
            Ws[c4 * 4 + 3][r] = v.w;
        }
        __syncthreads();
#pragma unroll
        for (int k = 0; k < 16; k++) {
            float a[8], w[4];
            *(float4*)(a)     = *(const float4*)&As[k][ty * 8];
            *(float4*)(a + 4) = *(const float4*)&As[k][ty * 8 + 4];
            *(float4*)(w)     = *(const float4*)&Ws[k][tx * 4];
#pragma unroll
            for (int i = 0; i < 8; i++)
#pragma unroll
                for (int j = 0; j < 4; j++) acc[i][j] += a[i] * w[j];
        }
        __syncthreads();
    }

#pragma unroll
    for (int j = 0; j < 4; j++) {
        int n = bn + tx * 4 + j;
        float bias = bih[n] + bhh[n];
#pragma unroll
        for (int i = 0; i < 8; i++) {
            int m = bm + ty * 8 + i;
            C[(long)m * GXN + n] = acc[i][j] + bias;
        }
    }
}

// ---------------------------------------------------------------------------
// 3) LSTM recurrence. 8 clusters of 8 CTAs. Per CTA: 128 gate rows, Whh rows
//    in registers as f32x2 pairs. Per step:
//      wait(mbar[p]) -> re-arm -> FFMA2 dot over h_buf[p] -> partial (+x)
//      -> __syncthreads -> 32 combiners: gates, c,h -> y STG
//      -> st.async h into all 8 CTAs' h_buf[p^1] / mbar[p^1]
// ---------------------------------------------------------------------------
__global__ void __cluster_dims__(8, 1, 1) __launch_bounds__(256, 1)
lstm_layer_kernel(const float* __restrict__ Whh, const float* __restrict__ gx,
                  float* __restrict__ y, const float* __restrict__ h0,
                  const float* __restrict__ c0, int layer)
{
    __shared__ __align__(16) float h_buf[2][256];
    __shared__ float partial[256];
    __shared__ __align__(8) ull mbar[2];

    unsigned rank;
    asm("mov.u32 %0, %%cluster_ctarank;" : "=r"(rank));
    const int cluster_id = blockIdx.x >> 3;
    const int group = cluster_id & 3;
    const int dir   = cluster_id >> 2;
    const int tid = threadIdx.x;
    const int row_local = tid & 127;
    const int half = tid >> 7;            // K-half: 0 -> k<128, 1 -> k>=128
    const int gate = row_local >> 5;      // 0..3 (i,f,g,o)
    const int ul   = row_local & 31;
    const int unit = (int)rank * 32 + ul;
    const int grow = gate * 256 + unit;   // global gate row 0..1023

    // --- Whh row (this thread's 128-wide K slice) into registers, f32x2 packed
    ulonglong2 w[32];
    const ulonglong2* wsrc = (const ulonglong2*)(Whh
        + ((long)(layer * 2 + dir) * 1024 + grow) * 256 + half * 128);
#pragma unroll
    for (int j = 0; j < 32; j++) w[j] = wsrc[j];

    // --- state init
    const int sidx = (layer * 2 + dir) * 256;
    h_buf[0][tid] = (group == 0) ? h0[sidx + tid] : 0.f;
    float creg = 0.f;
    if (tid < 32) creg = (group == 0) ? c0[sidx + (int)rank * 32 + tid] : 0.f;

    unsigned mb0 = smem_u32(&mbar[0]);
    unsigned mb1 = smem_u32(&mbar[1]);
    if (tid == 0) {
        mbar_init(mb0, 1);
        mbar_init(mb1, 1);
        mbar_arm(mb1, 1024);   // first use: step 1
        mbar_arm(mb0, 1024);   // first use: step 2
    }
    __syncthreads();
    cluster_sync_();           // barriers live everywhere before any st.async

    const int xcol = dir * 1024 + grow;
    const int ycol = dir * 256 + unit;
    const long mbase = (long)group * 32 * 128;
    unsigned ph0 = 0, ph1 = 0;

    // m index for linear step q (handles per-sample reversal for dir=1)
    auto midx = [&](int q) -> long {
        int t = q & 127;
        if (dir) t = 127 - t;
        return mbase + (q & ~127) + t;
    };

    float xcur = (tid < 128) ? __ldg(gx + midx(0) * GXN + xcol) : 0.f;

    for (int q = 0; q < 4096; q++) {
        const int p = q & 1;

        // prefetch next step's x before blocking
        float xnext = 0.f;
        if (tid < 128 && q + 1 < 4096)
            xnext = __ldg(gx + midx(q + 1) * GXN + xcol);

        if (q > 0) {
            if (p) { mbar_wait(mb1, ph1); ph1 ^= 1; }
            else   { mbar_wait(mb0, ph0); ph0 ^= 1; }
            if (tid == 0) mbar_arm(p ? mb1 : mb0, 1024);   // re-arm for q+2
        }

        // --- dot: 128 MACs as 64 FFMA2
        const ulonglong2* hb = ((const ulonglong2*)h_buf[p]) + half * 32;
        ull acc0 = 0, acc1 = 0;
#pragma unroll
        for (int j = 0; j < 32; j++) {
            ulonglong2 hv = hb[j];
            fma2(acc0, hv.x, w[j].x);
            fma2(acc1, hv.y, w[j].y);
        }
        float s = sum2(acc0) + sum2(acc1);
        partial[tid] = (tid < 128) ? (s + xcur) : s;
        __syncthreads();

        if (tid < 32) {
            float iv = partial[tid]      + partial[tid + 128];
            float fv = partial[tid + 32] + partial[tid + 160];
            float gv = partial[tid + 64] + partial[tid + 192];
            float ov = partial[tid + 96] + partial[tid + 224];
            float ig = sigmoid_fast(iv);
            float fg = sigmoid_fast(fv);
            float og = sigmoid_fast(ov);
            float gg = tanh_fast(gv);
            creg = fmaf(fg, creg, ig * gg);
            float h = og * tanh_fast(creg);
            y[midx(q) * Hn + ycol] = h;

            const int pn = p ^ 1;
            unsigned ldst = smem_u32(&h_buf[pn][(int)rank * 32 + tid]);
            unsigned lbar = pn ? mb1 : mb0;
#pragma unroll
            for (unsigned r = 0; r < 8; r++)
                st_async_f32(mapa_cluster(ldst, r), h, mapa_cluster(lbar, r));
        }
        xcur = xnext;
    }

    // absorb the final (unconsumed) broadcast, then leave together
    mbar_wait(mb0, ph0);
    cluster_sync_();
}

// ---------------------------------------------------------------------------
// 5) max over batch axis
// ---------------------------------------------------------------------------
__global__ void maxpool_kernel(const float* __restrict__ y1, float* __restrict__ out2)
{
    int idx = blockIdx.x * 256 + threadIdx.x;    // 0..65535
    int s = idx >> 9, h = idx & 511;
    float mx = -3.402823466e38f;
    for (int b = 0; b < 128; b++) {
        float v = y1[((long)b * 128 + s) * Hn + h];
        mx = fmaxf(mx, v);
    }
    out2[idx] = mx;
}

// ---------------------------------------------------------------------------
extern "C" void kernel_launch(void* const* d_in, const int* in_sizes, int n_in,
                              void* d_out, int out_size)
{
    const int*   rt  = (const int*)d_in[0];
    const int*   re  = (const int*)d_in[1];
    const int*   rm  = (const int*)d_in[2];
    const float* h0  = (const float*)d_in[3];
    const float* c0  = (const float*)d_in[4];
    const float* Ert = (const float*)d_in[5];
    const float* Ere = (const float*)d_in[6];
    const float* Erm = (const float*)d_in[7];
    const float* Wih = (const float*)d_in[8];   // (2,2,1024,512)
    const float* Whh = (const float*)d_in[9];   // (2,2,1024,256)
    const float* bih = (const float*)d_in[10];  // (2,2,1024)
    const float* bhh = (const float*)d_in[11];

    float* out  = (float*)d_out;
    float* y1   = out;                       // bilstm_outs (128,128,512)
    float* out2 = out + (long)Bn * Sn * Hn;  // output (128,512)

    void *p_emb = nullptr, *p_x = nullptr, *p_y0 = nullptr;
    cudaGetSymbolAddress(&p_emb, g_emb);
    cudaGetSymbolAddress(&p_x,   g_x);
    cudaGetSymbolAddress(&p_y0,  g_y0);
    float* emb = (float*)p_emb;
    float* gx  = (float*)p_x;
    float* y0  = (float*)p_y0;

    embed_kernel<<<NROW, 128>>>(rt, re, rm, Ert, Ere, Erm);

    dim3 ggrid(GXN / 64, NROW / 128);

    gemm_kernel<<<ggrid, 256>>>(emb, Wih, bih, bhh, gx);
    lstm_layer_kernel<<<64, 256>>>(Whh, gx, y0, h0, c0, 0);
    gemm_kernel<<<ggrid, 256>>>(y0, Wih + (long)1 * 2 * 1024 * 512,
                                bih + 2048, bhh + 2048, gx);
    lstm_layer_kernel<<<64, 256>>>(Whh, gx, y1, h0, c0, 1);
    maxpool_kernel<<<256, 256>>>(y1, out2);
}